// round 15
// baseline (speedup 1.0000x reference)
#include <cuda_runtime.h>
#include <cuda_fp16.h>
#include <cstdint>

#define BB   4
#define SS   2048
#define DD   1024
#define HH   16
#define DKK  64
#define GM   (BB*SS)
#define GK   DD
#define GN   DD

// ---------------------------------------------------------------------------
// Scratch (device globals; allocation-free per harness rules)
// ---------------------------------------------------------------------------
__device__ float gQ[BB*SS*DD];
__device__ float gK[BB*SS*DD];
__device__ float gV[BB*SS*DD];
__device__ float gC[BB*SS*DD];

// ---------------------------------------------------------------------------
// Helpers
// ---------------------------------------------------------------------------
__device__ __forceinline__ unsigned f2tf(float f) {
    unsigned r;
    asm("cvt.rna.tf32.f32 %0, %1;" : "=r"(r) : "f"(f));
    return r;
}
__device__ __forceinline__ float ex2(float x) {
    float r;
    asm("ex2.approx.ftz.f32 %0, %1;" : "=f"(r) : "f"(x));
    return r;
}
__device__ __forceinline__ unsigned packh2(float lo, float hi) {
    __half2 h = __floats2half2_rn(lo, hi);   // .x (low 16 bits) = lo
    return *(unsigned*)&h;
}
__device__ __forceinline__ void mma_tf32(float& d0, float& d1, float& d2, float& d3,
                                         unsigned a0, unsigned a1, unsigned a2, unsigned a3,
                                         unsigned b0, unsigned b1) {
    asm("mma.sync.aligned.m16n8k8.row.col.f32.tf32.tf32.f32 "
        "{%0,%1,%2,%3},{%4,%5,%6,%7},{%8,%9},{%0,%1,%2,%3};"
        : "+f"(d0), "+f"(d1), "+f"(d2), "+f"(d3)
        : "r"(a0), "r"(a1), "r"(a2), "r"(a3), "r"(b0), "r"(b1));
}
__device__ __forceinline__ void mma_f16(float& d0, float& d1, float& d2, float& d3,
                                        unsigned a0, unsigned a1, unsigned a2, unsigned a3,
                                        unsigned b0, unsigned b1) {
    asm("mma.sync.aligned.m16n8k16.row.col.f32.f16.f16.f32 "
        "{%0,%1,%2,%3},{%4,%5,%6,%7},{%8,%9},{%0,%1,%2,%3};"
        : "+f"(d0), "+f"(d1), "+f"(d2), "+f"(d3)
        : "r"(a0), "r"(a1), "r"(a2), "r"(a3), "r"(b0), "r"(b1));
}

// ---------------------------------------------------------------------------
// GEMM v6 = proven v3 + register prefetch of next-kt X/W tiles (the exact
// pattern that won in attn round 14). Staging phase is cvt+STS only; the
// LDGs for tile kt+1 issue right after the compute-ready sync and their
// latency overlaps the whole mma phase.
// CTA 128x128x32, 128 thr / 4 warps (2m x 2n), warp tile 64x64.
// ---------------------------------------------------------------------------
#define ASTR 36
#define BSTR 132

__global__ __launch_bounds__(128)
void gemm_bias(const float* __restrict__ X, const float* __restrict__ W,
               const float* __restrict__ bias, float* __restrict__ C, int round_out) {
    __shared__ unsigned As[128 * ASTR];
    __shared__ unsigned Bs[32 * BSTR];

    const int tid  = threadIdx.x;
    const int wid  = tid >> 5;
    const int lane = tid & 31;
    const int g    = lane >> 2;
    const int t    = lane & 3;
    const int wm   = wid & 1;
    const int wn   = wid >> 1;
    const int m0   = blockIdx.y * 128;
    const int n0   = blockIdx.x * 128;
    const int NKT  = GK / 32;
    // staging coordinates (fixed per thread)
    const int ar = tid >> 3, ac4 = tid & 7;     // A: row, float4-chunk
    const int br = tid >> 5, bc4g = tid & 31;   // B: row base, float4-chunk

    float acc[4][8][4];
#pragma unroll
    for (int mf = 0; mf < 4; mf++)
#pragma unroll
        for (int nf = 0; nf < 8; nf++)
#pragma unroll
            for (int r = 0; r < 4; r++) acc[mf][nf][r] = 0.f;

    // Prologue: prefetch tile kt=0 into registers
    float4 xr[8], wr[8];
#pragma unroll
    for (int i = 0; i < 8; i++) {
        int r = ar + (i & 1) * 64;               // rows ar, ar+64 alternating -> 8 chunks
        // simpler fixed map: chunk i covers rows ar with k-chunk pattern below
        xr[i] = *(const float4*)(X + (size_t)(m0 + ((tid + i * 128) >> 3)) * GK + ((tid + i * 128) & 7) * 4);
        wr[i] = *(const float4*)(W + (size_t)(((tid + i * 128) >> 5)) * GN + n0 + ((tid + i * 128) & 31) * 4);
        (void)r;
    }

    for (int kt = 0; kt < NKT; kt++) {
        __syncthreads();
        // staging: cvt + STS only (from prefetched registers)
#pragma unroll
        for (int i = 0; i < 8; i++) {
            int idx = tid + i * 128;
            int r = idx >> 3, c4 = idx & 7;
            unsigned* dst = &As[r * ASTR + c4 * 4];
            dst[0] = f2tf(xr[i].x); dst[1] = f2tf(xr[i].y);
            dst[2] = f2tf(xr[i].z); dst[3] = f2tf(xr[i].w);
        }
#pragma unroll
        for (int i = 0; i < 8; i++) {
            int idx = tid + i * 128;
            int r = idx >> 5, c4 = idx & 31;
            unsigned* dst = &Bs[r * BSTR + c4 * 4];
            dst[0] = f2tf(wr[i].x); dst[1] = f2tf(wr[i].y);
            dst[2] = f2tf(wr[i].z); dst[3] = f2tf(wr[i].w);
        }
        __syncthreads();

        // prefetch next tile: LDG latency hides behind the mma phase
        if (kt + 1 < NKT) {
#pragma unroll
            for (int i = 0; i < 8; i++) {
                int idx = tid + i * 128;
                int r = idx >> 3, c4 = idx & 7;
                xr[i] = *(const float4*)(X + (size_t)(m0 + r) * GK + (kt + 1) * 32 + c4 * 4);
                int rb = idx >> 5, cb = idx & 31;
                wr[i] = *(const float4*)(W + (size_t)((kt + 1) * 32 + rb) * GN + n0 + cb * 4);
            }
        }

#pragma unroll
        for (int ks = 0; ks < 4; ks++) {
            unsigned a[4][4];
#pragma unroll
            for (int mf = 0; mf < 4; mf++) {
                int rb = wm * 64 + mf * 16;
                a[mf][0] = As[(rb + g)     * ASTR + ks * 8 + t];
                a[mf][1] = As[(rb + g + 8) * ASTR + ks * 8 + t];
                a[mf][2] = As[(rb + g)     * ASTR + ks * 8 + t + 4];
                a[mf][3] = As[(rb + g + 8) * ASTR + ks * 8 + t + 4];
            }
#pragma unroll
            for (int nf = 0; nf < 8; nf++) {
                unsigned b0 = Bs[(ks * 8 + t)     * BSTR + wn * 64 + nf * 8 + g];
                unsigned b1 = Bs[(ks * 8 + t + 4) * BSTR + wn * 64 + nf * 8 + g];
#pragma unroll
                for (int mf = 0; mf < 4; mf++)
                    mma_tf32(acc[mf][nf][0], acc[mf][nf][1], acc[mf][nf][2], acc[mf][nf][3],
                             a[mf][0], a[mf][1], a[mf][2], a[mf][3], b0, b1);
            }
        }
    }

#pragma unroll
    for (int mf = 0; mf < 4; mf++) {
#pragma unroll
        for (int nf = 0; nf < 8; nf++) {
            int row = m0 + wm * 64 + mf * 16 + g;
            int col = n0 + wn * 64 + nf * 8 + 2 * t;
            float bv0 = bias[col], bv1 = bias[col + 1];
            float v00 = acc[mf][nf][0] + bv0;
            float v01 = acc[mf][nf][1] + bv1;
            float v10 = acc[mf][nf][2] + bv0;
            float v11 = acc[mf][nf][3] + bv1;
            if (round_out) {
                v00 = __uint_as_float(f2tf(v00));
                v01 = __uint_as_float(f2tf(v01));
                v10 = __uint_as_float(f2tf(v10));
                v11 = __uint_as_float(f2tf(v11));
            }
            C[(size_t)row * GN + col]           = v00;
            C[(size_t)row * GN + col + 1]       = v01;
            C[(size_t)(row + 8) * GN + col]     = v10;
            C[(size_t)(row + 8) * GN + col + 1] = v11;
        }
    }
}

// ---------------------------------------------------------------------------
// Flash attention v8 (PROVEN 400.8us, verbatim from round 14):
// QK^T tf32 (K permuted, register-prefetched), P*V fp16 m16n8k16.
// ---------------------------------------------------------------------------
#define KST 68
#define VST2 72
#define VOFF (128*KST)
#define ATTN_SMEM ((128*KST + 64*VST2) * 4)   // 53248 bytes

__global__ __launch_bounds__(256)
void attn_kernel(const float* __restrict__ gq, const float* __restrict__ gk,
                 const float* __restrict__ gv, float* __restrict__ gc) {
    extern __shared__ unsigned sm[];
    unsigned* Ks = sm;              // k-permuted tf32 [128][KST]
    unsigned* Vp = sm + VOFF;       // half2 row-pairs [64][VST2]

    const int b  = blockIdx.z;
    const int h  = blockIdx.y;
    const int q0 = blockIdx.x * 128;
    const int tid  = threadIdx.x;
    const int wid  = tid >> 5;
    const int lane = tid & 31;
    const int g    = lane >> 2;
    const int t    = lane & 3;
    const float L2E = 1.44269504f;

    unsigned qf[8][4];
    {
        const float* Qb = gq + ((size_t)(b * SS + q0 + wid * 16)) * DD + h * DKK;
#pragma unroll
        for (int ks = 0; ks < 8; ks++) {
            qf[ks][0] = __float_as_uint(Qb[(size_t)g * DD + ks * 8 + t] * 0.125f);
            qf[ks][1] = __float_as_uint(Qb[(size_t)(g + 8) * DD + ks * 8 + t] * 0.125f);
            qf[ks][2] = __float_as_uint(Qb[(size_t)g * DD + ks * 8 + t + 4] * 0.125f);
            qf[ks][3] = __float_as_uint(Qb[(size_t)(g + 8) * DD + ks * 8 + t + 4] * 0.125f);
        }
    }

    float mr0 = -1e30f, mr1 = -1e30f, l0 = 0.f, l1 = 0.f;
    float oacc[8][4];
#pragma unroll
    for (int nf = 0; nf < 8; nf++)
#pragma unroll
        for (int r = 0; r < 4; r++) oacc[nf][r] = 0.f;

    const uint4* Kb = (const uint4*)(gk + (size_t)b * SS * DD + h * DKK);
    const float* Vb = gv + (size_t)b * SS * DD + h * DKK;
    const int RSTR4 = DD / 4;
    const int sr = tid >> 4, sc4 = tid & 15;
    const int NT = SS / 128;

    uint4 kr[8];
#pragma unroll
    for (int i = 0; i < 8; i++)
        kr[i] = Kb[(size_t)(sr + i * 16) * RSTR4 + sc4];

    for (int kt = 0; kt < NT; kt++) {
        __syncthreads();
#pragma unroll
        for (int i = 0; i < 8; i++) {
            int r = sr + i * 16, c = sc4 * 4;
            int kbase = r * KST;
            Ks[kbase + ((c + 0) & 7) * 8 + ((c + 0) >> 3)] = kr[i].x;
            Ks[kbase + ((c + 1) & 7) * 8 + ((c + 1) >> 3)] = kr[i].y;
            Ks[kbase + ((c + 2) & 7) * 8 + ((c + 2) >> 3)] = kr[i].z;
            Ks[kbase + ((c + 3) & 7) * 8 + ((c + 3) >> 3)] = kr[i].w;
        }
#pragma unroll
        for (int i = 0; i < 4; i++) {
            int idx = tid + i * 256;
            int rp = idx >> 4, c4 = idx & 15;
            const float* g0 = Vb + (size_t)(kt * 128 + 2 * rp) * DD + c4 * 4;
            float4 va = *(const float4*)g0;
            float4 vb2 = *(const float4*)(g0 + DD);
            uint4 o;
            o.x = packh2(va.x, vb2.x);
            o.y = packh2(va.y, vb2.y);
            o.z = packh2(va.z, vb2.z);
            o.w = packh2(va.w, vb2.w);
            *(uint4*)&Vp[rp * VST2 + c4 * 4] = o;
        }
        __syncthreads();

        if (kt + 1 < NT) {
#pragma unroll
            for (int i = 0; i < 8; i++)
                kr[i] = Kb[(size_t)((kt + 1) * 128 + sr + i * 16) * RSTR4 + sc4];
        }

        float sacc[16][4];
#pragma unroll
        for (int nf = 0; nf < 16; nf++)
#pragma unroll
            for (int r = 0; r < 4; r++) sacc[nf][r] = 0.f;

#pragma unroll
        for (int nf = 0; nf < 16; nf++) {
            const uint4* kp = (const uint4*)&Ks[(nf * 8 + g) * KST + t * 8];
            uint4 k0 = kp[0], k1 = kp[1];
            const uint4* kq = (const uint4*)&Ks[(nf * 8 + g) * KST + (t + 4) * 8];
            uint4 k2 = kq[0], k3 = kq[1];
            mma_tf32(sacc[nf][0], sacc[nf][1], sacc[nf][2], sacc[nf][3],
                     qf[0][0], qf[0][1], qf[0][2], qf[0][3], k0.x, k2.x);
            mma_tf32(sacc[nf][0], sacc[nf][1], sacc[nf][2], sacc[nf][3],
                     qf[1][0], qf[1][1], qf[1][2], qf[1][3], k0.y, k2.y);
            mma_tf32(sacc[nf][0], sacc[nf][1], sacc[nf][2], sacc[nf][3],
                     qf[2][0], qf[2][1], qf[2][2], qf[2][3], k0.z, k2.z);
            mma_tf32(sacc[nf][0], sacc[nf][1], sacc[nf][2], sacc[nf][3],
                     qf[3][0], qf[3][1], qf[3][2], qf[3][3], k0.w, k2.w);
            mma_tf32(sacc[nf][0], sacc[nf][1], sacc[nf][2], sacc[nf][3],
                     qf[4][0], qf[4][1], qf[4][2], qf[4][3], k1.x, k3.x);
            mma_tf32(sacc[nf][0], sacc[nf][1], sacc[nf][2], sacc[nf][3],
                     qf[5][0], qf[5][1], qf[5][2], qf[5][3], k1.y, k3.y);
            mma_tf32(sacc[nf][0], sacc[nf][1], sacc[nf][2], sacc[nf][3],
                     qf[6][0], qf[6][1], qf[6][2], qf[6][3], k1.z, k3.z);
            mma_tf32(sacc[nf][0], sacc[nf][1], sacc[nf][2], sacc[nf][3],
                     qf[7][0], qf[7][1], qf[7][2], qf[7][3], k1.w, k3.w);
        }

        float rmax0 = -1e30f, rmax1 = -1e30f;
#pragma unroll
        for (int nf = 0; nf < 16; nf++) {
            rmax0 = fmaxf(rmax0, fmaxf(sacc[nf][0], sacc[nf][1]));
            rmax1 = fmaxf(rmax1, fmaxf(sacc[nf][2], sacc[nf][3]));
        }
        rmax0 = fmaxf(rmax0, __shfl_xor_sync(0xffffffffu, rmax0, 1));
        rmax0 = fmaxf(rmax0, __shfl_xor_sync(0xffffffffu, rmax0, 2));
        rmax1 = fmaxf(rmax1, __shfl_xor_sync(0xffffffffu, rmax1, 1));
        rmax1 = fmaxf(rmax1, __shfl_xor_sync(0xffffffffu, rmax1, 2));
        float mn0 = fmaxf(mr0, rmax0), mn1 = fmaxf(mr1, rmax1);
        float alpha0 = ex2((mr0 - mn0) * L2E);
        float alpha1 = ex2((mr1 - mn1) * L2E);
        mr0 = mn0; mr1 = mn1;

        unsigned pah[16][2];
        float rs0 = 0.f, rs1 = 0.f;
#pragma unroll
        for (int nf = 0; nf < 16; nf++) {
            float p0 = ex2((sacc[nf][0] - mn0) * L2E);
            float p1 = ex2((sacc[nf][1] - mn0) * L2E);
            float p2 = ex2((sacc[nf][2] - mn1) * L2E);
            float p3 = ex2((sacc[nf][3] - mn1) * L2E);
            rs0 += p0 + p1;
            rs1 += p2 + p3;
            pah[nf][0] = packh2(p0, p1);
            pah[nf][1] = packh2(p2, p3);
        }
        rs0 += __shfl_xor_sync(0xffffffffu, rs0, 1);
        rs0 += __shfl_xor_sync(0xffffffffu, rs0, 2);
        rs1 += __shfl_xor_sync(0xffffffffu, rs1, 1);
        rs1 += __shfl_xor_sync(0xffffffffu, rs1, 2);
        l0 = l0 * alpha0 + rs0;
        l1 = l1 * alpha1 + rs1;
#pragma unroll
        for (int nf = 0; nf < 8; nf++) {
            oacc[nf][0] *= alpha0; oacc[nf][1] *= alpha0;
            oacc[nf][2] *= alpha1; oacc[nf][3] *= alpha1;
        }

#pragma unroll
        for (int nf = 0; nf < 8; nf++) {
#pragma unroll
            for (int kp = 0; kp < 8; kp++) {
                unsigned b0 = Vp[(kp * 8 + t)     * VST2 + nf * 8 + g];
                unsigned b1 = Vp[(kp * 8 + t + 4) * VST2 + nf * 8 + g];
                mma_f16(oacc[nf][0], oacc[nf][1], oacc[nf][2], oacc[nf][3],
                        pah[2 * kp][0], pah[2 * kp][1],
                        pah[2 * kp + 1][0], pah[2 * kp + 1][1], b0, b1);
            }
        }
    }

    float inv0 = 1.f / l0, inv1 = 1.f / l1;
    float* Cb = gc + ((size_t)(b * SS + q0 + wid * 16)) * DD + h * DKK;
#pragma unroll
    for (int nf = 0; nf < 8; nf++) {
        int c = nf * 8 + 2 * t;
        Cb[(size_t)g * DD + c]           = __uint_as_float(f2tf(oacc[nf][0] * inv0));
        Cb[(size_t)g * DD + c + 1]       = __uint_as_float(f2tf(oacc[nf][1] * inv0));
        Cb[(size_t)(g + 8) * DD + c]     = __uint_as_float(f2tf(oacc[nf][2] * inv1));
        Cb[(size_t)(g + 8) * DD + c + 1] = __uint_as_float(f2tf(oacc[nf][3] * inv1));
    }
}

// ---------------------------------------------------------------------------
// Launch: 5 separate kernels.
// ---------------------------------------------------------------------------
extern "C" void kernel_launch(void* const* d_in, const int* in_sizes, int n_in,
                              void* d_out, int out_size) {
    const float* query = (const float*)d_in[0];
    const float* key_  = (const float*)d_in[1];
    const float* value = (const float*)d_in[2];
    const float* Wq = (const float*)d_in[3];
    const float* bq = (const float*)d_in[4];
    const float* Wk = (const float*)d_in[5];
    const float* bk = (const float*)d_in[6];
    const float* Wv = (const float*)d_in[7];
    const float* bv = (const float*)d_in[8];
    const float* Wo = (const float*)d_in[9];
    const float* bo = (const float*)d_in[10];
    float* out = (float*)d_out;

    float *pQ, *pK, *pV, *pC;
    cudaGetSymbolAddress((void**)&pQ, gQ);
    cudaGetSymbolAddress((void**)&pK, gK);
    cudaGetSymbolAddress((void**)&pV, gV);
    cudaGetSymbolAddress((void**)&pC, gC);

    cudaFuncSetAttribute(attn_kernel, cudaFuncAttributeMaxDynamicSharedMemorySize, ATTN_SMEM);

    dim3 ggrid(GN / 128, GM / 128);   // (8, 64)
    gemm_bias<<<ggrid, 128>>>(query, Wq, bq, pQ, 1);
    gemm_bias<<<ggrid, 128>>>(key_,  Wk, bk, pK, 1);
    gemm_bias<<<ggrid, 128>>>(value, Wv, bv, pV, 1);

    attn_kernel<<<dim3(SS / 128, HH, BB), 256, ATTN_SMEM>>>(pQ, pK, pV, pC);

    gemm_bias<<<ggrid, 128>>>(pC, Wo, bo, out, 0);
}

// round 16
// speedup vs baseline: 1.0536x; 1.0536x over previous
#include <cuda_runtime.h>
#include <cuda_fp16.h>
#include <cstdint>

#define BB   4
#define SS   2048
#define DD   1024
#define HH   16
#define DKK  64
#define GM   (BB*SS)
#define GK   DD
#define GN   DD

// ---------------------------------------------------------------------------
// Scratch (device globals; allocation-free per harness rules)
// ---------------------------------------------------------------------------
__device__ float gQ[BB*SS*DD];
__device__ float gK[BB*SS*DD];
__device__ float gV[BB*SS*DD];
__device__ float gC[BB*SS*DD];

// ---------------------------------------------------------------------------
// Helpers
// ---------------------------------------------------------------------------
__device__ __forceinline__ unsigned f2tf(float f) {
    unsigned r;
    asm("cvt.rna.tf32.f32 %0, %1;" : "=r"(r) : "f"(f));
    return r;
}
__device__ __forceinline__ float ex2(float x) {
    float r;
    asm("ex2.approx.ftz.f32 %0, %1;" : "=f"(r) : "f"(x));
    return r;
}
__device__ __forceinline__ unsigned packh2(float lo, float hi) {
    __half2 h = __floats2half2_rn(lo, hi);   // .x (low 16 bits) = lo
    return *(unsigned*)&h;
}
__device__ __forceinline__ void mma_tf32(float& d0, float& d1, float& d2, float& d3,
                                         unsigned a0, unsigned a1, unsigned a2, unsigned a3,
                                         unsigned b0, unsigned b1) {
    asm("mma.sync.aligned.m16n8k8.row.col.f32.tf32.tf32.f32 "
        "{%0,%1,%2,%3},{%4,%5,%6,%7},{%8,%9},{%0,%1,%2,%3};"
        : "+f"(d0), "+f"(d1), "+f"(d2), "+f"(d3)
        : "r"(a0), "r"(a1), "r"(a2), "r"(a3), "r"(b0), "r"(b1));
}
__device__ __forceinline__ void mma_f16(float& d0, float& d1, float& d2, float& d3,
                                        unsigned a0, unsigned a1, unsigned a2, unsigned a3,
                                        unsigned b0, unsigned b1) {
    asm("mma.sync.aligned.m16n8k16.row.col.f32.f16.f16.f32 "
        "{%0,%1,%2,%3},{%4,%5,%6,%7},{%8,%9},{%0,%1,%2,%3};"
        : "+f"(d0), "+f"(d1), "+f"(d2), "+f"(d3)
        : "r"(a0), "r"(a1), "r"(a2), "r"(a3), "r"(b0), "r"(b1));
}

// ---------------------------------------------------------------------------
// GEMM v7 = proven v3 + X-ONLY register prefetch (32 regs; W staging
// unchanged). Full X+W prefetch (round 15) spilled at 255 regs — this
// halves the dose to fit: ~200 regs, no spill.
// CTA 128x128x32, 128 thr / 4 warps (2m x 2n), warp tile 64x64.
// ---------------------------------------------------------------------------
#define ASTR 36
#define BSTR 132

__global__ __launch_bounds__(128)
void gemm_bias(const float* __restrict__ X, const float* __restrict__ W,
               const float* __restrict__ bias, float* __restrict__ C, int round_out) {
    __shared__ unsigned As[128 * ASTR];
    __shared__ unsigned Bs[32 * BSTR];

    const int tid  = threadIdx.x;
    const int wid  = tid >> 5;
    const int lane = tid & 31;
    const int g    = lane >> 2;
    const int t    = lane & 3;
    const int wm   = wid & 1;
    const int wn   = wid >> 1;
    const int m0   = blockIdx.y * 128;
    const int n0   = blockIdx.x * 128;
    const int NKT  = GK / 32;

    float acc[4][8][4];
#pragma unroll
    for (int mf = 0; mf < 4; mf++)
#pragma unroll
        for (int nf = 0; nf < 8; nf++)
#pragma unroll
            for (int r = 0; r < 4; r++) acc[mf][nf][r] = 0.f;

    // Prologue: prefetch X tile kt=0 into registers (8 x float4 = 32 regs)
    float4 xr[8];
#pragma unroll
    for (int i = 0; i < 8; i++) {
        int idx = tid + i * 128;
        int r = idx >> 3, c4 = idx & 7;
        xr[i] = *(const float4*)(X + (size_t)(m0 + r) * GK + c4 * 4);
    }

    for (int kt = 0; kt < NKT; kt++) {
        __syncthreads();
        // A staging: cvt + STS only (from prefetched registers)
#pragma unroll
        for (int i = 0; i < 8; i++) {
            int idx = tid + i * 128;
            int r = idx >> 3, c4 = idx & 7;
            unsigned* dst = &As[r * ASTR + c4 * 4];
            dst[0] = f2tf(xr[i].x); dst[1] = f2tf(xr[i].y);
            dst[2] = f2tf(xr[i].z); dst[3] = f2tf(xr[i].w);
        }
        // B staging: LDG -> cvt -> STS (unchanged from v3)
#pragma unroll
        for (int i = 0; i < 8; i++) {
            int idx = tid + i * 128;
            int r = idx >> 5, c4 = idx & 31;
            float4 v = *(const float4*)(W + (size_t)(kt * 32 + r) * GN + n0 + c4 * 4);
            unsigned* dst = &Bs[r * BSTR + c4 * 4];
            dst[0] = f2tf(v.x); dst[1] = f2tf(v.y); dst[2] = f2tf(v.z); dst[3] = f2tf(v.w);
        }
        __syncthreads();

        // Prefetch next X tile: LDG latency hides behind the mma phase
        if (kt + 1 < NKT) {
#pragma unroll
            for (int i = 0; i < 8; i++) {
                int idx = tid + i * 128;
                int r = idx >> 3, c4 = idx & 7;
                xr[i] = *(const float4*)(X + (size_t)(m0 + r) * GK + (kt + 1) * 32 + c4 * 4);
            }
        }

#pragma unroll
        for (int ks = 0; ks < 4; ks++) {
            unsigned a[4][4];
#pragma unroll
            for (int mf = 0; mf < 4; mf++) {
                int rb = wm * 64 + mf * 16;
                a[mf][0] = As[(rb + g)     * ASTR + ks * 8 + t];
                a[mf][1] = As[(rb + g + 8) * ASTR + ks * 8 + t];
                a[mf][2] = As[(rb + g)     * ASTR + ks * 8 + t + 4];
                a[mf][3] = As[(rb + g + 8) * ASTR + ks * 8 + t + 4];
            }
#pragma unroll
            for (int nf = 0; nf < 8; nf++) {
                unsigned b0 = Bs[(ks * 8 + t)     * BSTR + wn * 64 + nf * 8 + g];
                unsigned b1 = Bs[(ks * 8 + t + 4) * BSTR + wn * 64 + nf * 8 + g];
#pragma unroll
                for (int mf = 0; mf < 4; mf++)
                    mma_tf32(acc[mf][nf][0], acc[mf][nf][1], acc[mf][nf][2], acc[mf][nf][3],
                             a[mf][0], a[mf][1], a[mf][2], a[mf][3], b0, b1);
            }
        }
    }

#pragma unroll
    for (int mf = 0; mf < 4; mf++) {
#pragma unroll
        for (int nf = 0; nf < 8; nf++) {
            int row = m0 + wm * 64 + mf * 16 + g;
            int col = n0 + wn * 64 + nf * 8 + 2 * t;
            float bv0 = bias[col], bv1 = bias[col + 1];
            float v00 = acc[mf][nf][0] + bv0;
            float v01 = acc[mf][nf][1] + bv1;
            float v10 = acc[mf][nf][2] + bv0;
            float v11 = acc[mf][nf][3] + bv1;
            if (round_out) {
                v00 = __uint_as_float(f2tf(v00));
                v01 = __uint_as_float(f2tf(v01));
                v10 = __uint_as_float(f2tf(v10));
                v11 = __uint_as_float(f2tf(v11));
            }
            C[(size_t)row * GN + col]           = v00;
            C[(size_t)row * GN + col + 1]       = v01;
            C[(size_t)(row + 8) * GN + col]     = v10;
            C[(size_t)(row + 8) * GN + col + 1] = v11;
        }
    }
}

// ---------------------------------------------------------------------------
// Flash attention v8 (PROVEN 400.8us, verbatim from round 14):
// QK^T tf32 (K permuted, register-prefetched), P*V fp16 m16n8k16.
// ---------------------------------------------------------------------------
#define KST 68
#define VST2 72
#define VOFF (128*KST)
#define ATTN_SMEM ((128*KST + 64*VST2) * 4)   // 53248 bytes

__global__ __launch_bounds__(256)
void attn_kernel(const float* __restrict__ gq, const float* __restrict__ gk,
                 const float* __restrict__ gv, float* __restrict__ gc) {
    extern __shared__ unsigned sm[];
    unsigned* Ks = sm;              // k-permuted tf32 [128][KST]
    unsigned* Vp = sm + VOFF;       // half2 row-pairs [64][VST2]

    const int b  = blockIdx.z;
    const int h  = blockIdx.y;
    const int q0 = blockIdx.x * 128;
    const int tid  = threadIdx.x;
    const int wid  = tid >> 5;
    const int lane = tid & 31;
    const int g    = lane >> 2;
    const int t    = lane & 3;
    const float L2E = 1.44269504f;

    unsigned qf[8][4];
    {
        const float* Qb = gq + ((size_t)(b * SS + q0 + wid * 16)) * DD + h * DKK;
#pragma unroll
        for (int ks = 0; ks < 8; ks++) {
            qf[ks][0] = __float_as_uint(Qb[(size_t)g * DD + ks * 8 + t] * 0.125f);
            qf[ks][1] = __float_as_uint(Qb[(size_t)(g + 8) * DD + ks * 8 + t] * 0.125f);
            qf[ks][2] = __float_as_uint(Qb[(size_t)g * DD + ks * 8 + t + 4] * 0.125f);
            qf[ks][3] = __float_as_uint(Qb[(size_t)(g + 8) * DD + ks * 8 + t + 4] * 0.125f);
        }
    }

    float mr0 = -1e30f, mr1 = -1e30f, l0 = 0.f, l1 = 0.f;
    float oacc[8][4];
#pragma unroll
    for (int nf = 0; nf < 8; nf++)
#pragma unroll
        for (int r = 0; r < 4; r++) oacc[nf][r] = 0.f;

    const uint4* Kb = (const uint4*)(gk + (size_t)b * SS * DD + h * DKK);
    const float* Vb = gv + (size_t)b * SS * DD + h * DKK;
    const int RSTR4 = DD / 4;
    const int sr = tid >> 4, sc4 = tid & 15;
    const int NT = SS / 128;

    uint4 kr[8];
#pragma unroll
    for (int i = 0; i < 8; i++)
        kr[i] = Kb[(size_t)(sr + i * 16) * RSTR4 + sc4];

    for (int kt = 0; kt < NT; kt++) {
        __syncthreads();
#pragma unroll
        for (int i = 0; i < 8; i++) {
            int r = sr + i * 16, c = sc4 * 4;
            int kbase = r * KST;
            Ks[kbase + ((c + 0) & 7) * 8 + ((c + 0) >> 3)] = kr[i].x;
            Ks[kbase + ((c + 1) & 7) * 8 + ((c + 1) >> 3)] = kr[i].y;
            Ks[kbase + ((c + 2) & 7) * 8 + ((c + 2) >> 3)] = kr[i].z;
            Ks[kbase + ((c + 3) & 7) * 8 + ((c + 3) >> 3)] = kr[i].w;
        }
#pragma unroll
        for (int i = 0; i < 4; i++) {
            int idx = tid + i * 256;
            int rp = idx >> 4, c4 = idx & 15;
            const float* g0 = Vb + (size_t)(kt * 128 + 2 * rp) * DD + c4 * 4;
            float4 va = *(const float4*)g0;
            float4 vb2 = *(const float4*)(g0 + DD);
            uint4 o;
            o.x = packh2(va.x, vb2.x);
            o.y = packh2(va.y, vb2.y);
            o.z = packh2(va.z, vb2.z);
            o.w = packh2(va.w, vb2.w);
            *(uint4*)&Vp[rp * VST2 + c4 * 4] = o;
        }
        __syncthreads();

        if (kt + 1 < NT) {
#pragma unroll
            for (int i = 0; i < 8; i++)
                kr[i] = Kb[(size_t)((kt + 1) * 128 + sr + i * 16) * RSTR4 + sc4];
        }

        float sacc[16][4];
#pragma unroll
        for (int nf = 0; nf < 16; nf++)
#pragma unroll
            for (int r = 0; r < 4; r++) sacc[nf][r] = 0.f;

#pragma unroll
        for (int nf = 0; nf < 16; nf++) {
            const uint4* kp = (const uint4*)&Ks[(nf * 8 + g) * KST + t * 8];
            uint4 k0 = kp[0], k1 = kp[1];
            const uint4* kq = (const uint4*)&Ks[(nf * 8 + g) * KST + (t + 4) * 8];
            uint4 k2 = kq[0], k3 = kq[1];
            mma_tf32(sacc[nf][0], sacc[nf][1], sacc[nf][2], sacc[nf][3],
                     qf[0][0], qf[0][1], qf[0][2], qf[0][3], k0.x, k2.x);
            mma_tf32(sacc[nf][0], sacc[nf][1], sacc[nf][2], sacc[nf][3],
                     qf[1][0], qf[1][1], qf[1][2], qf[1][3], k0.y, k2.y);
            mma_tf32(sacc[nf][0], sacc[nf][1], sacc[nf][2], sacc[nf][3],
                     qf[2][0], qf[2][1], qf[2][2], qf[2][3], k0.z, k2.z);
            mma_tf32(sacc[nf][0], sacc[nf][1], sacc[nf][2], sacc[nf][3],
                     qf[3][0], qf[3][1], qf[3][2], qf[3][3], k0.w, k2.w);
            mma_tf32(sacc[nf][0], sacc[nf][1], sacc[nf][2], sacc[nf][3],
                     qf[4][0], qf[4][1], qf[4][2], qf[4][3], k1.x, k3.x);
            mma_tf32(sacc[nf][0], sacc[nf][1], sacc[nf][2], sacc[nf][3],
                     qf[5][0], qf[5][1], qf[5][2], qf[5][3], k1.y, k3.y);
            mma_tf32(sacc[nf][0], sacc[nf][1], sacc[nf][2], sacc[nf][3],
                     qf[6][0], qf[6][1], qf[6][2], qf[6][3], k1.z, k3.z);
            mma_tf32(sacc[nf][0], sacc[nf][1], sacc[nf][2], sacc[nf][3],
                     qf[7][0], qf[7][1], qf[7][2], qf[7][3], k1.w, k3.w);
        }

        float rmax0 = -1e30f, rmax1 = -1e30f;
#pragma unroll
        for (int nf = 0; nf < 16; nf++) {
            rmax0 = fmaxf(rmax0, fmaxf(sacc[nf][0], sacc[nf][1]));
            rmax1 = fmaxf(rmax1, fmaxf(sacc[nf][2], sacc[nf][3]));
        }
        rmax0 = fmaxf(rmax0, __shfl_xor_sync(0xffffffffu, rmax0, 1));
        rmax0 = fmaxf(rmax0, __shfl_xor_sync(0xffffffffu, rmax0, 2));
        rmax1 = fmaxf(rmax1, __shfl_xor_sync(0xffffffffu, rmax1, 1));
        rmax1 = fmaxf(rmax1, __shfl_xor_sync(0xffffffffu, rmax1, 2));
        float mn0 = fmaxf(mr0, rmax0), mn1 = fmaxf(mr1, rmax1);
        float alpha0 = ex2((mr0 - mn0) * L2E);
        float alpha1 = ex2((mr1 - mn1) * L2E);
        mr0 = mn0; mr1 = mn1;

        unsigned pah[16][2];
        float rs0 = 0.f, rs1 = 0.f;
#pragma unroll
        for (int nf = 0; nf < 16; nf++) {
            float p0 = ex2((sacc[nf][0] - mn0) * L2E);
            float p1 = ex2((sacc[nf][1] - mn0) * L2E);
            float p2 = ex2((sacc[nf][2] - mn1) * L2E);
            float p3 = ex2((sacc[nf][3] - mn1) * L2E);
            rs0 += p0 + p1;
            rs1 += p2 + p3;
            pah[nf][0] = packh2(p0, p1);
            pah[nf][1] = packh2(p2, p3);
        }
        rs0 += __shfl_xor_sync(0xffffffffu, rs0, 1);
        rs0 += __shfl_xor_sync(0xffffffffu, rs0, 2);
        rs1 += __shfl_xor_sync(0xffffffffu, rs1, 1);
        rs1 += __shfl_xor_sync(0xffffffffu, rs1, 2);
        l0 = l0 * alpha0 + rs0;
        l1 = l1 * alpha1 + rs1;
#pragma unroll
        for (int nf = 0; nf < 8; nf++) {
            oacc[nf][0] *= alpha0; oacc[nf][1] *= alpha0;
            oacc[nf][2] *= alpha1; oacc[nf][3] *= alpha1;
        }

#pragma unroll
        for (int nf = 0; nf < 8; nf++) {
#pragma unroll
            for (int kp = 0; kp < 8; kp++) {
                unsigned b0 = Vp[(kp * 8 + t)     * VST2 + nf * 8 + g];
                unsigned b1 = Vp[(kp * 8 + t + 4) * VST2 + nf * 8 + g];
                mma_f16(oacc[nf][0], oacc[nf][1], oacc[nf][2], oacc[nf][3],
                        pah[2 * kp][0], pah[2 * kp][1],
                        pah[2 * kp + 1][0], pah[2 * kp + 1][1], b0, b1);
            }
        }
    }

    float inv0 = 1.f / l0, inv1 = 1.f / l1;
    float* Cb = gc + ((size_t)(b * SS + q0 + wid * 16)) * DD + h * DKK;
#pragma unroll
    for (int nf = 0; nf < 8; nf++) {
        int c = nf * 8 + 2 * t;
        Cb[(size_t)g * DD + c]           = __uint_as_float(f2tf(oacc[nf][0] * inv0));
        Cb[(size_t)g * DD + c + 1]       = __uint_as_float(f2tf(oacc[nf][1] * inv0));
        Cb[(size_t)(g + 8) * DD + c]     = __uint_as_float(f2tf(oacc[nf][2] * inv1));
        Cb[(size_t)(g + 8) * DD + c + 1] = __uint_as_float(f2tf(oacc[nf][3] * inv1));
    }
}

// ---------------------------------------------------------------------------
// Launch: 5 separate kernels.
// ---------------------------------------------------------------------------
extern "C" void kernel_launch(void* const* d_in, const int* in_sizes, int n_in,
                              void* d_out, int out_size) {
    const float* query = (const float*)d_in[0];
    const float* key_  = (const float*)d_in[1];
    const float* value = (const float*)d_in[2];
    const float* Wq = (const float*)d_in[3];
    const float* bq = (const float*)d_in[4];
    const float* Wk = (const float*)d_in[5];
    const float* bk = (const float*)d_in[6];
    const float* Wv = (const float*)d_in[7];
    const float* bv = (const float*)d_in[8];
    const float* Wo = (const float*)d_in[9];
    const float* bo = (const float*)d_in[10];
    float* out = (float*)d_out;

    float *pQ, *pK, *pV, *pC;
    cudaGetSymbolAddress((void**)&pQ, gQ);
    cudaGetSymbolAddress((void**)&pK, gK);
    cudaGetSymbolAddress((void**)&pV, gV);
    cudaGetSymbolAddress((void**)&pC, gC);

    cudaFuncSetAttribute(attn_kernel, cudaFuncAttributeMaxDynamicSharedMemorySize, ATTN_SMEM);

    dim3 ggrid(GN / 128, GM / 128);   // (8, 64)
    gemm_bias<<<ggrid, 128>>>(query, Wq, bq, pQ, 1);
    gemm_bias<<<ggrid, 128>>>(key_,  Wk, bk, pK, 1);
    gemm_bias<<<ggrid, 128>>>(value, Wv, bv, pV, 1);

    attn_kernel<<<dim3(SS / 128, HH, BB), 256, ATTN_SMEM>>>(pQ, pK, pV, pC);

    gemm_bias<<<ggrid, 128>>>(pC, Wo, bo, out, 0);
}

// round 17
// speedup vs baseline: 1.1085x; 1.0521x over previous
#include <cuda_runtime.h>
#include <cuda_fp16.h>
#include <cstdint>

#define BB   4
#define SS   2048
#define DD   1024
#define HH   16
#define DKK  64
#define GM   (BB*SS)
#define GK   DD
#define GN   DD

// ---------------------------------------------------------------------------
// Scratch (device globals; allocation-free per harness rules)
// ---------------------------------------------------------------------------
__device__ float gQ[BB*SS*DD];
__device__ float gK[BB*SS*DD];
__device__ float gV[BB*SS*DD];
__device__ float gC[BB*SS*DD];

// ---------------------------------------------------------------------------
// Helpers
// ---------------------------------------------------------------------------
__device__ __forceinline__ unsigned f2tf(float f) {
    unsigned r;
    asm("cvt.rna.tf32.f32 %0, %1;" : "=r"(r) : "f"(f));
    return r;
}
__device__ __forceinline__ float ex2(float x) {
    float r;
    asm("ex2.approx.ftz.f32 %0, %1;" : "=f"(r) : "f"(x));
    return r;
}
__device__ __forceinline__ unsigned packh2(float lo, float hi) {
    __half2 h = __floats2half2_rn(lo, hi);   // .x (low 16 bits) = lo
    return *(unsigned*)&h;
}
__device__ __forceinline__ void mma_tf32(float& d0, float& d1, float& d2, float& d3,
                                         unsigned a0, unsigned a1, unsigned a2, unsigned a3,
                                         unsigned b0, unsigned b1) {
    asm("mma.sync.aligned.m16n8k8.row.col.f32.tf32.tf32.f32 "
        "{%0,%1,%2,%3},{%4,%5,%6,%7},{%8,%9},{%0,%1,%2,%3};"
        : "+f"(d0), "+f"(d1), "+f"(d2), "+f"(d3)
        : "r"(a0), "r"(a1), "r"(a2), "r"(a3), "r"(b0), "r"(b1));
}
__device__ __forceinline__ void mma_f16(float& d0, float& d1, float& d2, float& d3,
                                        unsigned a0, unsigned a1, unsigned a2, unsigned a3,
                                        unsigned b0, unsigned b1) {
    asm("mma.sync.aligned.m16n8k16.row.col.f32.f16.f16.f32 "
        "{%0,%1,%2,%3},{%4,%5,%6,%7},{%8,%9},{%0,%1,%2,%3};"
        : "+f"(d0), "+f"(d1), "+f"(d2), "+f"(d3)
        : "r"(a0), "r"(a1), "r"(a2), "r"(a3), "r"(b0), "r"(b1));
}

// ---------------------------------------------------------------------------
// GEMM core (v7, proven ~131us/call): tf32, CTA 128x128x32, 128 thr / 4 warps
// (2m x 2n), warp tile 64x64, X register-prefetch (32 regs).
// ---------------------------------------------------------------------------
#define ASTR 36
#define BSTR 132

__device__ __forceinline__ void gemm_body(
    const float* __restrict__ X, const float* __restrict__ W,
    const float* __restrict__ bias, float* __restrict__ C, int round_out,
    int m0, int n0, unsigned* As, unsigned* Bs)
{
    const int tid  = threadIdx.x;
    const int wid  = tid >> 5;
    const int lane = tid & 31;
    const int g    = lane >> 2;
    const int t    = lane & 3;
    const int wm   = wid & 1;
    const int wn   = wid >> 1;
    const int NKT  = GK / 32;

    float acc[4][8][4];
#pragma unroll
    for (int mf = 0; mf < 4; mf++)
#pragma unroll
        for (int nf = 0; nf < 8; nf++)
#pragma unroll
            for (int r = 0; r < 4; r++) acc[mf][nf][r] = 0.f;

    // Prologue: prefetch X tile kt=0 into registers (8 x float4 = 32 regs)
    float4 xr[8];
#pragma unroll
    for (int i = 0; i < 8; i++) {
        int idx = tid + i * 128;
        int r = idx >> 3, c4 = idx & 7;
        xr[i] = *(const float4*)(X + (size_t)(m0 + r) * GK + c4 * 4);
    }

    for (int kt = 0; kt < NKT; kt++) {
        __syncthreads();
        // A staging: cvt + STS only (from prefetched registers)
#pragma unroll
        for (int i = 0; i < 8; i++) {
            int idx = tid + i * 128;
            int r = idx >> 3, c4 = idx & 7;
            unsigned* dst = &As[r * ASTR + c4 * 4];
            dst[0] = f2tf(xr[i].x); dst[1] = f2tf(xr[i].y);
            dst[2] = f2tf(xr[i].z); dst[3] = f2tf(xr[i].w);
        }
        // B staging: LDG -> cvt -> STS
#pragma unroll
        for (int i = 0; i < 8; i++) {
            int idx = tid + i * 128;
            int r = idx >> 5, c4 = idx & 31;
            float4 v = *(const float4*)(W + (size_t)(kt * 32 + r) * GN + n0 + c4 * 4);
            unsigned* dst = &Bs[r * BSTR + c4 * 4];
            dst[0] = f2tf(v.x); dst[1] = f2tf(v.y); dst[2] = f2tf(v.z); dst[3] = f2tf(v.w);
        }
        __syncthreads();

        // Prefetch next X tile: LDG latency hides behind the mma phase
        if (kt + 1 < NKT) {
#pragma unroll
            for (int i = 0; i < 8; i++) {
                int idx = tid + i * 128;
                int r = idx >> 3, c4 = idx & 7;
                xr[i] = *(const float4*)(X + (size_t)(m0 + r) * GK + (kt + 1) * 32 + c4 * 4);
            }
        }

#pragma unroll
        for (int ks = 0; ks < 4; ks++) {
            unsigned a[4][4];
#pragma unroll
            for (int mf = 0; mf < 4; mf++) {
                int rb = wm * 64 + mf * 16;
                a[mf][0] = As[(rb + g)     * ASTR + ks * 8 + t];
                a[mf][1] = As[(rb + g + 8) * ASTR + ks * 8 + t];
                a[mf][2] = As[(rb + g)     * ASTR + ks * 8 + t + 4];
                a[mf][3] = As[(rb + g + 8) * ASTR + ks * 8 + t + 4];
            }
#pragma unroll
            for (int nf = 0; nf < 8; nf++) {
                unsigned b0 = Bs[(ks * 8 + t)     * BSTR + wn * 64 + nf * 8 + g];
                unsigned b1 = Bs[(ks * 8 + t + 4) * BSTR + wn * 64 + nf * 8 + g];
#pragma unroll
                for (int mf = 0; mf < 4; mf++)
                    mma_tf32(acc[mf][nf][0], acc[mf][nf][1], acc[mf][nf][2], acc[mf][nf][3],
                             a[mf][0], a[mf][1], a[mf][2], a[mf][3], b0, b1);
            }
        }
    }

#pragma unroll
    for (int mf = 0; mf < 4; mf++) {
#pragma unroll
        for (int nf = 0; nf < 8; nf++) {
            int row = m0 + wm * 64 + mf * 16 + g;
            int col = n0 + wn * 64 + nf * 8 + 2 * t;
            float bv0 = bias[col], bv1 = bias[col + 1];
            float v00 = acc[mf][nf][0] + bv0;
            float v01 = acc[mf][nf][1] + bv1;
            float v10 = acc[mf][nf][2] + bv0;
            float v11 = acc[mf][nf][3] + bv1;
            if (round_out) {
                v00 = __uint_as_float(f2tf(v00));
                v01 = __uint_as_float(f2tf(v01));
                v10 = __uint_as_float(f2tf(v10));
                v11 = __uint_as_float(f2tf(v11));
            }
            C[(size_t)row * GN + col]           = v00;
            C[(size_t)row * GN + col + 1]       = v01;
            C[(size_t)(row + 8) * GN + col]     = v10;
            C[(size_t)(row + 8) * GN + col + 1] = v11;
        }
    }
}

// Fused QKV projections: grid.z selects tensor set via uniform ternaries
// (NOT struct indexing — that forced local-memory spills in round 8).
__global__ __launch_bounds__(128)
void gemm_qkv(const float* __restrict__ xq, const float* __restrict__ xk,
              const float* __restrict__ xv,
              const float* __restrict__ Wq, const float* __restrict__ Wk,
              const float* __restrict__ Wv,
              const float* __restrict__ bq, const float* __restrict__ bk,
              const float* __restrict__ bv,
              float* __restrict__ cq, float* __restrict__ ck, float* __restrict__ cv) {
    __shared__ unsigned As[128 * ASTR];
    __shared__ unsigned Bs[32 * BSTR];
    const int z = blockIdx.z;
    const float* X    = (z == 0) ? xq : (z == 1) ? xk : xv;
    const float* W    = (z == 0) ? Wq : (z == 1) ? Wk : Wv;
    const float* bias = (z == 0) ? bq : (z == 1) ? bk : bv;
    float* C          = (z == 0) ? cq : (z == 1) ? ck : cv;
    gemm_body(X, W, bias, C, 1, blockIdx.y * 128, blockIdx.x * 128, As, Bs);
}

__global__ __launch_bounds__(128)
void gemm_bias(const float* __restrict__ X, const float* __restrict__ W,
               const float* __restrict__ bias, float* __restrict__ C, int round_out) {
    __shared__ unsigned As[128 * ASTR];
    __shared__ unsigned Bs[32 * BSTR];
    gemm_body(X, W, bias, C, round_out, blockIdx.y * 128, blockIdx.x * 128, As, Bs);
}

// ---------------------------------------------------------------------------
// Flash attention v8 (PROVEN 399.6us, verbatim):
// QK^T tf32 (K permuted, register-prefetched), P*V fp16 m16n8k16.
// ---------------------------------------------------------------------------
#define KST 68
#define VST2 72
#define VOFF (128*KST)
#define ATTN_SMEM ((128*KST + 64*VST2) * 4)   // 53248 bytes

__global__ __launch_bounds__(256)
void attn_kernel(const float* __restrict__ gq, const float* __restrict__ gk,
                 const float* __restrict__ gv, float* __restrict__ gc) {
    extern __shared__ unsigned sm[];
    unsigned* Ks = sm;              // k-permuted tf32 [128][KST]
    unsigned* Vp = sm + VOFF;       // half2 row-pairs [64][VST2]

    const int b  = blockIdx.z;
    const int h  = blockIdx.y;
    const int q0 = blockIdx.x * 128;
    const int tid  = threadIdx.x;
    const int wid  = tid >> 5;
    const int lane = tid & 31;
    const int g    = lane >> 2;
    const int t    = lane & 3;
    const float L2E = 1.44269504f;

    unsigned qf[8][4];
    {
        const float* Qb = gq + ((size_t)(b * SS + q0 + wid * 16)) * DD + h * DKK;
#pragma unroll
        for (int ks = 0; ks < 8; ks++) {
            qf[ks][0] = __float_as_uint(Qb[(size_t)g * DD + ks * 8 + t] * 0.125f);
            qf[ks][1] = __float_as_uint(Qb[(size_t)(g + 8) * DD + ks * 8 + t] * 0.125f);
            qf[ks][2] = __float_as_uint(Qb[(size_t)g * DD + ks * 8 + t + 4] * 0.125f);
            qf[ks][3] = __float_as_uint(Qb[(size_t)(g + 8) * DD + ks * 8 + t + 4] * 0.125f);
        }
    }

    float mr0 = -1e30f, mr1 = -1e30f, l0 = 0.f, l1 = 0.f;
    float oacc[8][4];
#pragma unroll
    for (int nf = 0; nf < 8; nf++)
#pragma unroll
        for (int r = 0; r < 4; r++) oacc[nf][r] = 0.f;

    const uint4* Kb = (const uint4*)(gk + (size_t)b * SS * DD + h * DKK);
    const float* Vb = gv + (size_t)b * SS * DD + h * DKK;
    const int RSTR4 = DD / 4;
    const int sr = tid >> 4, sc4 = tid & 15;
    const int NT = SS / 128;

    uint4 kr[8];
#pragma unroll
    for (int i = 0; i < 8; i++)
        kr[i] = Kb[(size_t)(sr + i * 16) * RSTR4 + sc4];

    for (int kt = 0; kt < NT; kt++) {
        __syncthreads();
#pragma unroll
        for (int i = 0; i < 8; i++) {
            int r = sr + i * 16, c = sc4 * 4;
            int kbase = r * KST;
            Ks[kbase + ((c + 0) & 7) * 8 + ((c + 0) >> 3)] = kr[i].x;
            Ks[kbase + ((c + 1) & 7) * 8 + ((c + 1) >> 3)] = kr[i].y;
            Ks[kbase + ((c + 2) & 7) * 8 + ((c + 2) >> 3)] = kr[i].z;
            Ks[kbase + ((c + 3) & 7) * 8 + ((c + 3) >> 3)] = kr[i].w;
        }
#pragma unroll
        for (int i = 0; i < 4; i++) {
            int idx = tid + i * 256;
            int rp = idx >> 4, c4 = idx & 15;
            const float* g0 = Vb + (size_t)(kt * 128 + 2 * rp) * DD + c4 * 4;
            float4 va = *(const float4*)g0;
            float4 vb2 = *(const float4*)(g0 + DD);
            uint4 o;
            o.x = packh2(va.x, vb2.x);
            o.y = packh2(va.y, vb2.y);
            o.z = packh2(va.z, vb2.z);
            o.w = packh2(va.w, vb2.w);
            *(uint4*)&Vp[rp * VST2 + c4 * 4] = o;
        }
        __syncthreads();

        if (kt + 1 < NT) {
#pragma unroll
            for (int i = 0; i < 8; i++)
                kr[i] = Kb[(size_t)((kt + 1) * 128 + sr + i * 16) * RSTR4 + sc4];
        }

        float sacc[16][4];
#pragma unroll
        for (int nf = 0; nf < 16; nf++)
#pragma unroll
            for (int r = 0; r < 4; r++) sacc[nf][r] = 0.f;

#pragma unroll
        for (int nf = 0; nf < 16; nf++) {
            const uint4* kp = (const uint4*)&Ks[(nf * 8 + g) * KST + t * 8];
            uint4 k0 = kp[0], k1 = kp[1];
            const uint4* kq = (const uint4*)&Ks[(nf * 8 + g) * KST + (t + 4) * 8];
            uint4 k2 = kq[0], k3 = kq[1];
            mma_tf32(sacc[nf][0], sacc[nf][1], sacc[nf][2], sacc[nf][3],
                     qf[0][0], qf[0][1], qf[0][2], qf[0][3], k0.x, k2.x);
            mma_tf32(sacc[nf][0], sacc[nf][1], sacc[nf][2], sacc[nf][3],
                     qf[1][0], qf[1][1], qf[1][2], qf[1][3], k0.y, k2.y);
            mma_tf32(sacc[nf][0], sacc[nf][1], sacc[nf][2], sacc[nf][3],
                     qf[2][0], qf[2][1], qf[2][2], qf[2][3], k0.z, k2.z);
            mma_tf32(sacc[nf][0], sacc[nf][1], sacc[nf][2], sacc[nf][3],
                     qf[3][0], qf[3][1], qf[3][2], qf[3][3], k0.w, k2.w);
            mma_tf32(sacc[nf][0], sacc[nf][1], sacc[nf][2], sacc[nf][3],
                     qf[4][0], qf[4][1], qf[4][2], qf[4][3], k1.x, k3.x);
            mma_tf32(sacc[nf][0], sacc[nf][1], sacc[nf][2], sacc[nf][3],
                     qf[5][0], qf[5][1], qf[5][2], qf[5][3], k1.y, k3.y);
            mma_tf32(sacc[nf][0], sacc[nf][1], sacc[nf][2], sacc[nf][3],
                     qf[6][0], qf[6][1], qf[6][2], qf[6][3], k1.z, k3.z);
            mma_tf32(sacc[nf][0], sacc[nf][1], sacc[nf][2], sacc[nf][3],
                     qf[7][0], qf[7][1], qf[7][2], qf[7][3], k1.w, k3.w);
        }

        float rmax0 = -1e30f, rmax1 = -1e30f;
#pragma unroll
        for (int nf = 0; nf < 16; nf++) {
            rmax0 = fmaxf(rmax0, fmaxf(sacc[nf][0], sacc[nf][1]));
            rmax1 = fmaxf(rmax1, fmaxf(sacc[nf][2], sacc[nf][3]));
        }
        rmax0 = fmaxf(rmax0, __shfl_xor_sync(0xffffffffu, rmax0, 1));
        rmax0 = fmaxf(rmax0, __shfl_xor_sync(0xffffffffu, rmax0, 2));
        rmax1 = fmaxf(rmax1, __shfl_xor_sync(0xffffffffu, rmax1, 1));
        rmax1 = fmaxf(rmax1, __shfl_xor_sync(0xffffffffu, rmax1, 2));
        float mn0 = fmaxf(mr0, rmax0), mn1 = fmaxf(mr1, rmax1);
        float alpha0 = ex2((mr0 - mn0) * L2E);
        float alpha1 = ex2((mr1 - mn1) * L2E);
        mr0 = mn0; mr1 = mn1;

        unsigned pah[16][2];
        float rs0 = 0.f, rs1 = 0.f;
#pragma unroll
        for (int nf = 0; nf < 16; nf++) {
            float p0 = ex2((sacc[nf][0] - mn0) * L2E);
            float p1 = ex2((sacc[nf][1] - mn0) * L2E);
            float p2 = ex2((sacc[nf][2] - mn1) * L2E);
            float p3 = ex2((sacc[nf][3] - mn1) * L2E);
            rs0 += p0 + p1;
            rs1 += p2 + p3;
            pah[nf][0] = packh2(p0, p1);
            pah[nf][1] = packh2(p2, p3);
        }
        rs0 += __shfl_xor_sync(0xffffffffu, rs0, 1);
        rs0 += __shfl_xor_sync(0xffffffffu, rs0, 2);
        rs1 += __shfl_xor_sync(0xffffffffu, rs1, 1);
        rs1 += __shfl_xor_sync(0xffffffffu, rs1, 2);
        l0 = l0 * alpha0 + rs0;
        l1 = l1 * alpha1 + rs1;
#pragma unroll
        for (int nf = 0; nf < 8; nf++) {
            oacc[nf][0] *= alpha0; oacc[nf][1] *= alpha0;
            oacc[nf][2] *= alpha1; oacc[nf][3] *= alpha1;
        }

#pragma unroll
        for (int nf = 0; nf < 8; nf++) {
#pragma unroll
            for (int kp = 0; kp < 8; kp++) {
                unsigned b0 = Vp[(kp * 8 + t)     * VST2 + nf * 8 + g];
                unsigned b1 = Vp[(kp * 8 + t + 4) * VST2 + nf * 8 + g];
                mma_f16(oacc[nf][0], oacc[nf][1], oacc[nf][2], oacc[nf][3],
                        pah[2 * kp][0], pah[2 * kp][1],
                        pah[2 * kp + 1][0], pah[2 * kp + 1][1], b0, b1);
            }
        }
    }

    float inv0 = 1.f / l0, inv1 = 1.f / l1;
    float* Cb = gc + ((size_t)(b * SS + q0 + wid * 16)) * DD + h * DKK;
#pragma unroll
    for (int nf = 0; nf < 8; nf++) {
        int c = nf * 8 + 2 * t;
        Cb[(size_t)g * DD + c]           = __uint_as_float(f2tf(oacc[nf][0] * inv0));
        Cb[(size_t)g * DD + c + 1]       = __uint_as_float(f2tf(oacc[nf][1] * inv0));
        Cb[(size_t)(g + 8) * DD + c]     = __uint_as_float(f2tf(oacc[nf][2] * inv1));
        Cb[(size_t)(g + 8) * DD + c + 1] = __uint_as_float(f2tf(oacc[nf][3] * inv1));
    }
}

// ---------------------------------------------------------------------------
// Launch: fused QKV (1) + attention (1) + output projection (1).
// ---------------------------------------------------------------------------
extern "C" void kernel_launch(void* const* d_in, const int* in_sizes, int n_in,
                              void* d_out, int out_size) {
    const float* query = (const float*)d_in[0];
    const float* key_  = (const float*)d_in[1];
    const float* value = (const float*)d_in[2];
    const float* Wq = (const float*)d_in[3];
    const float* bq = (const float*)d_in[4];
    const float* Wk = (const float*)d_in[5];
    const float* bk = (const float*)d_in[6];
    const float* Wv = (const float*)d_in[7];
    const float* bv = (const float*)d_in[8];
    const float* Wo = (const float*)d_in[9];
    const float* bo = (const float*)d_in[10];
    float* out = (float*)d_out;

    float *pQ, *pK, *pV, *pC;
    cudaGetSymbolAddress((void**)&pQ, gQ);
    cudaGetSymbolAddress((void**)&pK, gK);
    cudaGetSymbolAddress((void**)&pV, gV);
    cudaGetSymbolAddress((void**)&pC, gC);

    cudaFuncSetAttribute(attn_kernel, cudaFuncAttributeMaxDynamicSharedMemorySize, ATTN_SMEM);

    gemm_qkv<<<dim3(GN / 128, GM / 128, 3), 128>>>(
        query, key_, value, Wq, Wk, Wv, bq, bk, bv, pQ, pK, pV);

    attn_kernel<<<dim3(SS / 128, HH, BB), 256, ATTN_SMEM>>>(pQ, pK, pV, pC);

    gemm_bias<<<dim3(GN / 128, GM / 128), 128>>>(pC, Wo, bo, out, 0);
}